// round 1
// baseline (speedup 1.0000x reference)
#include <cuda_runtime.h>
#include <cstdint>

// Problem constants
#define BB 8
#define CC 256
#define FHH 64
#define FWW 64
#define SS (FHH * FWW)        // 4096 spatial positions per batch
#define NN 131072
#define MARGIN 12.0f

#define GATHER_BLOCKS (NN / 8) // 8 samples (warps) per block -> 16384 blocks

// Scratch: channels-last transposed copies (B, S, C). 32MB each.
__device__ float g_q_t[(size_t)BB * SS * CC];
__device__ float g_r_t[(size_t)BB * SS * CC];
__device__ float g_partials[GATHER_BLOCKS];

// ---------------------------------------------------------------------------
// Tiled transpose: in[(b*C + c)*S + s]  ->  out[(b*S + s)*C + c]
// One block = one 32x32 (c,s) tile. Block (32,8), each thread covers 4 rows.
// Reads coalesced along s, writes coalesced along c.
// ---------------------------------------------------------------------------
__global__ void transpose_kernel(const float* __restrict__ in, float* __restrict__ out) {
    __shared__ float tile[32][33];

    const int b      = blockIdx.z;
    const int c_tile = blockIdx.y * 32;
    const int s_tile = blockIdx.x * 32;
    const int tx = threadIdx.x;
    const int ty = threadIdx.y;

    const float* src = in + ((size_t)b * CC) * SS;

#pragma unroll
    for (int j = 0; j < 4; j++) {
        int c = c_tile + ty + j * 8;
        tile[ty + j * 8][tx] = src[(size_t)c * SS + (s_tile + tx)];
    }
    __syncthreads();

    float* dst = out + (size_t)b * SS * CC;
#pragma unroll
    for (int j = 0; j < 4; j++) {
        int s = s_tile + ty + j * 8;
        dst[(size_t)s * CC + (c_tile + tx)] = tile[tx][ty + j * 8];
    }
}

// ---------------------------------------------------------------------------
// Gather + triplet loss. One warp per sample. Each lane reads 2 float4
// chunks per vector (256 floats / 32 lanes = 8 floats = 2x float4).
// Fully coalesced 1KB reads per vector from the channels-last copies.
// Deterministic per-block partial sums (no float atomics).
// ---------------------------------------------------------------------------
__global__ void __launch_bounds__(256)
gather_loss_kernel(const int* __restrict__ batch_idx,
                   const int* __restrict__ anchor_yx,
                   const int* __restrict__ pos_yx,
                   const int* __restrict__ neg_yx) {
    const int warp = threadIdx.x >> 5;
    const int lane = threadIdx.x & 31;
    const int i = blockIdx.x * 8 + warp;   // grid sized exactly: i < NN always

    const int b  = batch_idx[i];
    const int ay = anchor_yx[2 * i], ax = anchor_yx[2 * i + 1];
    const int py = pos_yx[2 * i],    px = pos_yx[2 * i + 1];
    const int ny = neg_yx[2 * i],    nx = neg_yx[2 * i + 1];

    const float4* av = (const float4*)&g_q_t[((size_t)b * SS + ay * FWW + ax) * CC];
    const float4* pv = (const float4*)&g_r_t[((size_t)b * SS + py * FWW + px) * CC];
    const float4* nv = (const float4*)&g_r_t[((size_t)b * SS + ny * FWW + nx) * CC];

    float dp = 0.0f, dn = 0.0f;
#pragma unroll
    for (int k = 0; k < 2; k++) {
        float4 a = av[lane + k * 32];
        float4 p = pv[lane + k * 32];
        float4 n = nv[lane + k * 32];
        float d;
        d = a.x - p.x; dp = fmaf(d, d, dp);
        d = a.y - p.y; dp = fmaf(d, d, dp);
        d = a.z - p.z; dp = fmaf(d, d, dp);
        d = a.w - p.w; dp = fmaf(d, d, dp);
        d = a.x - n.x; dn = fmaf(d, d, dn);
        d = a.y - n.y; dn = fmaf(d, d, dn);
        d = a.z - n.z; dn = fmaf(d, d, dn);
        d = a.w - n.w; dn = fmaf(d, d, dn);
    }

#pragma unroll
    for (int off = 16; off > 0; off >>= 1) {
        dp += __shfl_xor_sync(0xFFFFFFFFu, dp, off);
        dn += __shfl_xor_sync(0xFFFFFFFFu, dn, off);
    }

    __shared__ float s_loss[8];
    if (lane == 0)
        s_loss[warp] = fmaxf(dp - dn + MARGIN, 0.0f);
    __syncthreads();

    if (threadIdx.x == 0) {
        float t = 0.0f;
#pragma unroll
        for (int w = 0; w < 8; w++) t += s_loss[w];
        g_partials[blockIdx.x] = t;
    }
}

// ---------------------------------------------------------------------------
// Final deterministic reduction of 16384 partials -> scalar.
// ---------------------------------------------------------------------------
__global__ void __launch_bounds__(256)
finalize_kernel(float* __restrict__ out) {
    __shared__ float s[256];
    float t = 0.0f;
    for (int j = threadIdx.x; j < GATHER_BLOCKS; j += 256)
        t += g_partials[j];
    s[threadIdx.x] = t;
    __syncthreads();
#pragma unroll
    for (int st = 128; st > 0; st >>= 1) {
        if (threadIdx.x < st) s[threadIdx.x] += s[threadIdx.x + st];
        __syncthreads();
    }
    if (threadIdx.x == 0)
        out[0] = s[0] / (1e-6f + (float)NN);
}

extern "C" void kernel_launch(void* const* d_in, const int* in_sizes, int n_in,
                              void* d_out, int out_size) {
    const float* q    = (const float*)d_in[0]; // sketch_query_vectors (B,C,FH,FW)
    const float* r    = (const float*)d_in[1]; // ref_key_vectors      (B,C,FH,FW)
    const int* bidx   = (const int*)d_in[2];   // batch_idx (N)
    const int* a_yx   = (const int*)d_in[3];   // anchor_yx (N,2)
    const int* p_yx   = (const int*)d_in[4];   // pos_yx    (N,2)
    const int* n_yx   = (const int*)d_in[5];   // neg_yx    (N,2)
    float* out = (float*)d_out;

    // 1) Transpose both tensors to channels-last.
    float* q_t_ptr; cudaGetSymbolAddress((void**)&q_t_ptr, g_q_t);
    float* r_t_ptr; cudaGetSymbolAddress((void**)&r_t_ptr, g_r_t);

    dim3 tgrid(SS / 32, CC / 32, BB);   // (128, 8, 8)
    dim3 tblk(32, 8);
    transpose_kernel<<<tgrid, tblk>>>(q, q_t_ptr);
    transpose_kernel<<<tgrid, tblk>>>(r, r_t_ptr);

    // 2) Gather + per-sample loss + per-block partials.
    gather_loss_kernel<<<GATHER_BLOCKS, 256>>>(bidx, a_yx, p_yx, n_yx);

    // 3) Final reduce.
    finalize_kernel<<<1, 256>>>(out);
}

// round 2
// speedup vs baseline: 1.4739x; 1.4739x over previous
#include <cuda_runtime.h>
#include <cuda_bf16.h>
#include <cstdint>

// Problem constants
#define BB 8
#define CC 256
#define FHH 64
#define FWW 64
#define SS (FHH * FWW)          // 4096 spatial positions per batch
#define NN 131072
#define MARGIN 12.0f

#define SPW 8                   // samples per warp in gather
#define GBLOCKS (NN / (8 * SPW))  // 2048 gather blocks (8 warps/block)

// Scratch: channels-last bf16 copies (B, S, C). 16MB each -> both fit L2.
__device__ __nv_bfloat16 g_q_b[(size_t)BB * SS * CC];
__device__ __nv_bfloat16 g_r_b[(size_t)BB * SS * CC];
__device__ float g_partials[GBLOCKS];
__device__ unsigned int g_count = 0;

// ---------------------------------------------------------------------------
// Fused transpose+downconvert: f32 NCHW -> bf16 (B, S, C) for BOTH tensors.
// grid = (S/32, C/64, 2*B); z < B handles q, z >= B handles r.
// Tile: 64 channels x 32 spatial. Reads 128B/warp coalesced; writes 128B/warp
// coalesced bf16x2. Shared layout [s][c] with pad -> conflict-free.
// ---------------------------------------------------------------------------
__global__ void __launch_bounds__(256)
transpose_bf16_kernel(const float* __restrict__ q, const float* __restrict__ r) {
    __shared__ __nv_bfloat16 tile[32][66];   // [s_local][c_local], 2-elem pad

    const int z = blockIdx.z;
    const float* in = (z < BB) ? q : r;
    __nv_bfloat16* out = (z < BB) ? g_q_b : g_r_b;
    const int b  = z & (BB - 1);
    const int c0 = blockIdx.y * 64;
    const int s0 = blockIdx.x * 32;
    const int tx = threadIdx.x;
    const int ty = threadIdx.y;

    const float* src = in + (size_t)b * CC * SS;
#pragma unroll
    for (int j = 0; j < 8; j++) {
        int cl = ty + j * 8;                 // 0..63
        tile[tx][cl] = __float2bfloat16(src[(size_t)(c0 + cl) * SS + s0 + tx]);
    }
    __syncthreads();

    __nv_bfloat16* dst = out + (size_t)b * SS * CC;
#pragma unroll
    for (int j = 0; j < 4; j++) {
        int sl = ty + j * 8;                 // 0..31
        __nv_bfloat162 v = *(const __nv_bfloat162*)&tile[sl][2 * tx];
        *(__nv_bfloat162*)&dst[(size_t)(s0 + sl) * CC + c0 + 2 * tx] = v;
    }
}

// ---------------------------------------------------------------------------
// Gather + triplet loss + full reduction (last-block pattern).
// One warp handles SPW samples; per sample each lane reads ONE uint4 (8 bf16)
// from each of a/p/n -> 512B coalesced per vector per warp.
// ---------------------------------------------------------------------------
__device__ __forceinline__ void acc_sqdiff(unsigned int au, unsigned int bu, float& s) {
    float2 a = __bfloat1622float2(*(const __nv_bfloat162*)&au);
    float2 b = __bfloat1622float2(*(const __nv_bfloat162*)&bu);
    float d0 = a.x - b.x;
    float d1 = a.y - b.y;
    s = fmaf(d0, d0, s);
    s = fmaf(d1, d1, s);
}

__global__ void __launch_bounds__(256)
gather_loss_kernel(const int* __restrict__ batch_idx,
                   const int* __restrict__ anchor_yx,
                   const int* __restrict__ pos_yx,
                   const int* __restrict__ neg_yx,
                   float* __restrict__ out) {
    const int warp = threadIdx.x >> 5;
    const int lane = threadIdx.x & 31;
    const int base = (blockIdx.x * 8 + warp) * SPW;

    float acc = 0.0f;
#pragma unroll 2
    for (int t = 0; t < SPW; t++) {
        const int i  = base + t;
        const int b  = batch_idx[i];
        const int ay = anchor_yx[2 * i], ax = anchor_yx[2 * i + 1];
        const int py = pos_yx[2 * i],    px = pos_yx[2 * i + 1];
        const int ny = neg_yx[2 * i],    nx = neg_yx[2 * i + 1];

        const uint4* av = (const uint4*)&g_q_b[((size_t)b * SS + ay * FWW + ax) * CC];
        const uint4* pv = (const uint4*)&g_r_b[((size_t)b * SS + py * FWW + px) * CC];
        const uint4* nv = (const uint4*)&g_r_b[((size_t)b * SS + ny * FWW + nx) * CC];

        const uint4 ar = av[lane];
        const uint4 pr = pv[lane];
        const uint4 nr = nv[lane];

        float dp = 0.0f, dn = 0.0f;
        acc_sqdiff(ar.x, pr.x, dp);  acc_sqdiff(ar.y, pr.y, dp);
        acc_sqdiff(ar.z, pr.z, dp);  acc_sqdiff(ar.w, pr.w, dp);
        acc_sqdiff(ar.x, nr.x, dn);  acc_sqdiff(ar.y, nr.y, dn);
        acc_sqdiff(ar.z, nr.z, dn);  acc_sqdiff(ar.w, nr.w, dn);

        float diff = dp - dn;
#pragma unroll
        for (int off = 16; off > 0; off >>= 1)
            diff += __shfl_xor_sync(0xFFFFFFFFu, diff, off);

        acc += fmaxf(diff + MARGIN, 0.0f);
    }

    // Block reduce: 8 warp sums -> 1 partial
    __shared__ float s_loss[8];
    __shared__ bool s_last;
    __shared__ float s_red[256];

    if (lane == 0) s_loss[warp] = acc;
    __syncthreads();

    if (threadIdx.x == 0) {
        float bs = 0.0f;
#pragma unroll
        for (int w = 0; w < 8; w++) bs += s_loss[w];
        g_partials[blockIdx.x] = bs;
        __threadfence();
        unsigned int c = atomicAdd(&g_count, 1u);
        s_last = (c == (unsigned int)(GBLOCKS - 1));
    }
    __syncthreads();

    // Last block to arrive reduces all partials (deterministic order).
    if (s_last) {
        volatile float* vp = g_partials;
        float t = 0.0f;
        for (int j = threadIdx.x; j < GBLOCKS; j += 256) t += vp[j];
        s_red[threadIdx.x] = t;
        __syncthreads();
#pragma unroll
        for (int st = 128; st > 0; st >>= 1) {
            if (threadIdx.x < st) s_red[threadIdx.x] += s_red[threadIdx.x + st];
            __syncthreads();
        }
        if (threadIdx.x == 0) {
            out[0] = s_red[0] / (1e-6f + (float)NN);
            g_count = 0;   // reset for next graph replay
        }
    }
}

extern "C" void kernel_launch(void* const* d_in, const int* in_sizes, int n_in,
                              void* d_out, int out_size) {
    const float* q  = (const float*)d_in[0]; // sketch_query_vectors (B,C,FH,FW)
    const float* r  = (const float*)d_in[1]; // ref_key_vectors      (B,C,FH,FW)
    const int* bidx = (const int*)d_in[2];   // batch_idx (N)
    const int* a_yx = (const int*)d_in[3];   // anchor_yx (N,2)
    const int* p_yx = (const int*)d_in[4];   // pos_yx    (N,2)
    const int* n_yx = (const int*)d_in[5];   // neg_yx    (N,2)
    float* out = (float*)d_out;

    dim3 tgrid(SS / 32, CC / 64, 2 * BB);    // (128, 4, 16)
    transpose_bf16_kernel<<<tgrid, dim3(32, 8)>>>(q, r);

    gather_loss_kernel<<<GBLOCKS, 256>>>(bidx, a_yx, p_yx, n_yx, out);
}

// round 3
// speedup vs baseline: 1.5741x; 1.0680x over previous
#include <cuda_runtime.h>
#include <cuda_bf16.h>
#include <cstdint>

// Problem constants
#define BB 8
#define CC 256
#define FHH 64
#define FWW 64
#define SS (FHH * FWW)          // 4096 spatial positions per batch
#define NN 131072
#define MARGIN 12.0f

#define GBLOCKS (NN / 256)      // 512 gather blocks (8 warps x 32 samples)

// Scratch: channels-last bf16 copies (B, S, C). 16MB each -> both fit L2.
__device__ __nv_bfloat16 g_q_b[(size_t)BB * SS * CC];
__device__ __nv_bfloat16 g_r_b[(size_t)BB * SS * CC];
// Per-position squared-norm partials for r: 4 c-tile partials per position.
__device__ float4 g_rn[(size_t)BB * SS];
__device__ float g_partials[GBLOCKS];
__device__ unsigned int g_count = 0;

// ---------------------------------------------------------------------------
// Fused transpose + downconvert + r-norm partials.
// f32 NCHW -> bf16 (B, S, C) for BOTH tensors; for r also computes per-position
// partial sum of squares over this block's 64 channels (from the bf16-rounded
// values, so the norm identity is exact w.r.t. the stored vectors).
// grid = (S/32, C/64, 2*B); z < B handles q, z >= B handles r.
// ---------------------------------------------------------------------------
__global__ void __launch_bounds__(256)
transpose_bf16_kernel(const float* __restrict__ q, const float* __restrict__ r) {
    __shared__ __nv_bfloat16 tile[32][66];   // [s_local][c_local], pad -> conflict-free
    __shared__ float npart[8][33];

    const int z = blockIdx.z;
    const bool isR = (z >= BB);
    const float* in = isR ? r : q;
    __nv_bfloat16* out = isR ? g_r_b : g_q_b;
    const int b  = z & (BB - 1);
    const int c0 = blockIdx.y * 64;
    const int s0 = blockIdx.x * 32;
    const int tx = threadIdx.x;
    const int ty = threadIdx.y;

    const float* src = in + (size_t)b * CC * SS;
    float ps = 0.0f;
#pragma unroll
    for (int j = 0; j < 8; j++) {
        int cl = ty * 8 + j;                 // channel within tile: 0..63
        __nv_bfloat16 vb = __float2bfloat16(src[(size_t)(c0 + cl) * SS + s0 + tx]);
        tile[tx][cl] = vb;
        float vf = __bfloat162float(vb);
        ps = fmaf(vf, vf, ps);
    }
    if (isR) npart[ty][tx] = ps;
    __syncthreads();

    __nv_bfloat16* dst = out + (size_t)b * SS * CC;
#pragma unroll
    for (int j = 0; j < 4; j++) {
        int sl = ty + j * 8;                 // 0..31
        __nv_bfloat162 v = *(const __nv_bfloat162*)&tile[sl][2 * tx];
        *(__nv_bfloat162*)&dst[(size_t)(s0 + sl) * CC + c0 + 2 * tx] = v;
    }

    if (isR && ty == 0) {
        float t = 0.0f;
#pragma unroll
        for (int k = 0; k < 8; k++) t += npart[k][tx];
        ((float*)g_rn)[((size_t)b * SS + s0 + tx) * 4 + blockIdx.y] = t;
    }
}

// ---------------------------------------------------------------------------
// Gather + triplet loss + full reduction.
// Each lane owns one sample's index prologue; the warp then processes its 32
// samples with 4 SHFL broadcasts + 3 coalesced uint4 loads per sample.
// Per sample: dp-dn = ||p||^2 - ||n||^2 - 2 a.(p-n); only a.(p-n) is reduced.
// ---------------------------------------------------------------------------
__device__ __forceinline__ void dot2(unsigned int ua, unsigned int up,
                                     unsigned int un, float& dot) {
    __nv_bfloat162 d2 = __hsub2(*(const __nv_bfloat162*)&up,
                                *(const __nv_bfloat162*)&un);
    float2 df = __bfloat1622float2(d2);
    float2 af = __bfloat1622float2(*(const __nv_bfloat162*)&ua);
    dot = fmaf(af.x, df.x, dot);
    dot = fmaf(af.y, df.y, dot);
}

__global__ void __launch_bounds__(256)
gather_loss_kernel(const int* __restrict__ batch_idx,
                   const int* __restrict__ anchor_yx,
                   const int* __restrict__ pos_yx,
                   const int* __restrict__ neg_yx,
                   float* __restrict__ out) {
    const int warp = threadIdx.x >> 5;
    const int lane = threadIdx.x & 31;
    const int i = (blockIdx.x * 8 + warp) * 32 + lane;   // this lane's sample

    // Prologue: per-lane sample index math (coalesced loads).
    const int b = batch_idx[i];
    const int2 ayx = ((const int2*)anchor_yx)[i];
    const int2 pyx = ((const int2*)pos_yx)[i];
    const int2 nyx = ((const int2*)neg_yx)[i];
    const int posP = b * SS + pyx.x * FWW + pyx.y;
    const int posN = b * SS + nyx.x * FWW + nyx.y;
    const int offA = (b * SS + ayx.x * FWW + ayx.y) * CC;
    const int offP = posP * CC;
    const int offN = posN * CC;
    const float4 np4 = g_rn[posP];
    const float4 nn4 = g_rn[posN];
    const float ndm = ((np4.x + np4.y) + (np4.z + np4.w))
                    - ((nn4.x + nn4.y) + (nn4.z + nn4.w)) + MARGIN;

    const int le = lane * 8;   // element offset within a 256-elem vector
    float acc = 0.0f;

#pragma unroll 4
    for (int t = 0; t < 32; t++) {
        const int oA = __shfl_sync(0xFFFFFFFFu, offA, t);
        const int oP = __shfl_sync(0xFFFFFFFFu, offP, t);
        const int oN = __shfl_sync(0xFFFFFFFFu, offN, t);
        const float nd = __shfl_sync(0xFFFFFFFFu, ndm, t);

        const uint4 av = *(const uint4*)(g_q_b + oA + le);
        const uint4 pv = *(const uint4*)(g_r_b + oP + le);
        const uint4 nv = *(const uint4*)(g_r_b + oN + le);

        float dot = 0.0f;
        dot2(av.x, pv.x, nv.x, dot);
        dot2(av.y, pv.y, nv.y, dot);
        dot2(av.z, pv.z, nv.z, dot);
        dot2(av.w, pv.w, nv.w, dot);

#pragma unroll
        for (int off = 16; off > 0; off >>= 1)
            dot += __shfl_xor_sync(0xFFFFFFFFu, dot, off);

        acc += fmaxf(fmaf(-2.0f, dot, nd), 0.0f);   // relu(dp-dn+margin)
    }

    // acc is warp-uniform after the butterfly. Block reduce: 8 warp values.
    __shared__ float s_loss[8];
    __shared__ bool s_last;
    __shared__ float s_red[256];

    if (lane == 0) s_loss[warp] = acc;
    __syncthreads();

    if (threadIdx.x == 0) {
        float bs = 0.0f;
#pragma unroll
        for (int w = 0; w < 8; w++) bs += s_loss[w];
        g_partials[blockIdx.x] = bs;
        __threadfence();
        unsigned int c = atomicAdd(&g_count, 1u);
        s_last = (c == (unsigned int)(GBLOCKS - 1));
    }
    __syncthreads();

    // Last block to arrive reduces all partials (deterministic order).
    if (s_last) {
        volatile float* vp = g_partials;
        float t = 0.0f;
        for (int j = threadIdx.x; j < GBLOCKS; j += 256) t += vp[j];
        s_red[threadIdx.x] = t;
        __syncthreads();
#pragma unroll
        for (int st = 128; st > 0; st >>= 1) {
            if (threadIdx.x < st) s_red[threadIdx.x] += s_red[threadIdx.x + st];
            __syncthreads();
        }
        if (threadIdx.x == 0) {
            out[0] = s_red[0] / (1e-6f + (float)NN);
            g_count = 0;   // reset for next graph replay
        }
    }
}

extern "C" void kernel_launch(void* const* d_in, const int* in_sizes, int n_in,
                              void* d_out, int out_size) {
    const float* q  = (const float*)d_in[0]; // sketch_query_vectors (B,C,FH,FW)
    const float* r  = (const float*)d_in[1]; // ref_key_vectors      (B,C,FH,FW)
    const int* bidx = (const int*)d_in[2];   // batch_idx (N)
    const int* a_yx = (const int*)d_in[3];   // anchor_yx (N,2)
    const int* p_yx = (const int*)d_in[4];   // pos_yx    (N,2)
    const int* n_yx = (const int*)d_in[5];   // neg_yx    (N,2)
    float* out = (float*)d_out;

    dim3 tgrid(SS / 32, CC / 64, 2 * BB);    // (128, 4, 16)
    transpose_bf16_kernel<<<tgrid, dim3(32, 8)>>>(q, r);

    gather_loss_kernel<<<GBLOCKS, 256>>>(bidx, a_yx, p_yx, n_yx, out);
}